// round 13
// baseline (speedup 1.0000x reference)
#include <cuda_runtime.h>
#include <cuda_bf16.h>
#include <cstdint>
#include <math.h>

#define B_ROWS 8192
#define KNN    32
#define D      512
#define KP     1536   // logical concatenated K (3*D)

// 1/sqrt(512)
#define SCORE_SCALE 0.044194173824159220f

// -------- device scratch (allocation-free) --------
__device__ __align__(16) __nv_bfloat16 g_W_hi[(size_t)D * D];     // [n][d]
__device__ __align__(16) __nv_bfloat16 g_W_lo[(size_t)D * D];     // [n][d]
__device__ __align__(16) __nv_bfloat16 g_x_hi[(size_t)B_ROWS * D];
__device__ __align__(16) __nv_bfloat16 g_x_lo[(size_t)B_ROWS * D];
__device__ float g_c[D];
__device__ float g_u[D];
__device__ float g_s0;
__device__ __align__(16) float g_q2[(size_t)B_ROWS * D];

// ---- PTX helpers ----
__device__ __forceinline__ uint32_t smem_to_u32(const void* p) {
    uint32_t a;
    asm("{ .reg .u64 tmp; cvta.to.shared.u64 tmp, %1; cvt.u32.u64 %0, tmp; }"
        : "=r"(a) : "l"(p));
    return a;
}
__device__ __forceinline__ void mma_bf16_16816(float* d, const uint32_t* a, const uint32_t* b) {
    asm volatile(
        "mma.sync.aligned.m16n8k16.row.col.f32.bf16.bf16.f32 "
        "{%0,%1,%2,%3}, {%4,%5,%6,%7}, {%8,%9}, {%0,%1,%2,%3};"
        : "+f"(d[0]), "+f"(d[1]), "+f"(d[2]), "+f"(d[3])
        : "r"(a[0]), "r"(a[1]), "r"(a[2]), "r"(a[3]), "r"(b[0]), "r"(b[1]));
}
__device__ __forceinline__ void ldsm_x4(uint32_t& r0, uint32_t& r1, uint32_t& r2, uint32_t& r3,
                                        uint32_t addr) {
    asm volatile("ldmatrix.sync.aligned.m8n8.x4.shared.b16 {%0,%1,%2,%3}, [%4];"
                 : "=r"(r0), "=r"(r1), "=r"(r2), "=r"(r3) : "r"(addr));
}
#define CP_ASYNC_16(dst, src) \
    asm volatile("cp.async.cg.shared.global [%0], [%1], 16;" :: "r"(dst), "l"(src))
#define CP_COMMIT() asm volatile("cp.async.commit_group;" ::: "memory")
#define CP_WAIT1()  asm volatile("cp.async.wait_group 1;" ::: "memory")

// per-K'-tile source selection (logical [x_hi | x_hi | x_lo], [W_hi | W_lo | W_hi])
__device__ __forceinline__ const __nv_bfloat16* a_src(int ko) {
    return (ko < 1024) ? (g_x_hi + (ko & 511)) : (g_x_lo + (ko - 1024));
}
__device__ __forceinline__ const __nv_bfloat16* b_src(int ko) {
    return (ko < 512) ? (g_W_hi + ko)
         : (ko < 1024) ? (g_W_lo + (ko - 512))
                       : (g_W_hi + (ko - 1024));
}

// ============================================================
// Kernel 1 (merged): blocks [0,256) = prep_W 32x32 tile
// (register double-buffered k-loop); blocks [256,288) = prep_aux.
// ============================================================
#define PREP_W_BLOCKS   256
#define PREP_AUX_BLOCKS 32
#define PREP_GRID (PREP_W_BLOCKS + PREP_AUX_BLOCKS)

__global__ __launch_bounds__(256) void k_prep_W(const float* __restrict__ w1,
                                                const float* __restrict__ w2,
                                                const float* __restrict__ b1,
                                                const float* __restrict__ b2) {
    const int bid = blockIdx.x;
    const int t   = threadIdx.x;

    if (bid < PREP_W_BLOCKS) {
        // ---- role: prep_W (double-buffered loads) ----
        __shared__ __align__(16) float As[32][36];
        __shared__ __align__(16) float Bs[32][36];
        const int tx = t & 31;
        const int ty = t >> 5;
        const int m0 = (bid >> 4) * 32;
        const int n0 = (bid & 15) * 32;
        const int lrow = t >> 3;
        const int lcol = (t & 7) * 4;

        float acc[4] = {0.f, 0.f, 0.f, 0.f};

        const float* w1p = w1 + (size_t)lrow * D + m0 + lcol;
        const float* w2p = w2 + (size_t)lrow * D + n0 + lcol;

        float4 a = *(const float4*)(w1p);
        float4 b = *(const float4*)(w2p);

        for (int k0 = 0; k0 < D; k0 += 32) {
            *(float4*)&As[lrow][lcol] = a;
            *(float4*)&Bs[lrow][lcol] = b;
            __syncthreads();
            if (k0 + 32 < D) {
                a = *(const float4*)(w1p + (size_t)(k0 + 32) * D);
                b = *(const float4*)(w2p + (size_t)(k0 + 32) * D);
            }
#pragma unroll
            for (int k = 0; k < 32; k++) {
                const float bv = Bs[k][tx];
#pragma unroll
                for (int i = 0; i < 4; i++) acc[i] += As[k][ty * 4 + i] * bv;
            }
            __syncthreads();
        }
        const int mbase = m0 + ty * 4;
        const int n = n0 + tx;
        __nv_bfloat16 h4[4], l4[4];
#pragma unroll
        for (int i = 0; i < 4; i++) {
            h4[i] = __float2bfloat16_rn(acc[i]);
            l4[i] = __float2bfloat16_rn(acc[i] - __bfloat162float(h4[i]));
        }
        *(uint2*)(g_W_hi + (size_t)n * D + mbase) = *(const uint2*)h4;
        *(uint2*)(g_W_lo + (size_t)n * D + mbase) = *(const uint2*)l4;

    } else {
        // ---- role: prep_aux ----
        const int ab = bid - PREP_W_BLOCKS;
        const int dl = t >> 4;
        const int el = t & 15;
        const int d = ab * 16 + dl;
        float cacc = 0.f, uacc = 0.f;
#pragma unroll 4
        for (int e = el; e < D; e += 16) {
            cacc += b1[e] * w2[(size_t)e * D + d];
            uacc += b2[e] * w1[(size_t)e * D + d];
        }
#pragma unroll
        for (int o = 8; o; o >>= 1) {
            cacc += __shfl_down_sync(0xffffffffu, cacc, o, 16);
            uacc += __shfl_down_sync(0xffffffffu, uacc, o, 16);
        }
        if (el == 0) { g_c[d] = cacc; g_u[d] = uacc; }
        if (ab == 0 && t < 32) {
            float s = 0.f;
            for (int e = t; e < D; e += 32) s += b1[e] * b2[e];
#pragma unroll
            for (int o = 16; o; o >>= 1) s += __shfl_xor_sync(0xffffffffu, s, o);
            if (t == 0) g_s0 = s;
        }
    }
}

// ============================================================
// Kernel 2b: split x -> g_x_hi / g_x_lo.
// ============================================================
__global__ __launch_bounds__(256) void k_split_x(const float* __restrict__ x) {
    const size_t base = ((size_t)blockIdx.x * 256 + threadIdx.x) * 8;
    float4 v0 = *(const float4*)(x + base);
    float4 v1 = *(const float4*)(x + base + 4);
    float f[8] = {v0.x, v0.y, v0.z, v0.w, v1.x, v1.y, v1.z, v1.w};
    __nv_bfloat16 hi[8], lo[8];
#pragma unroll
    for (int i = 0; i < 8; i++) {
        hi[i] = __float2bfloat16_rn(f[i]);
        lo[i] = __float2bfloat16_rn(f[i] - __bfloat162float(hi[i]));
    }
    *(uint4*)(g_x_hi + base) = *(const uint4*)hi;
    *(uint4*)(g_x_lo + base) = *(const uint4*)lo;
}

// ============================================================
// Kernel 3 (R9/R11 exact): q2 = [xhi|xhi|xlo] @ [Whi|Wlo|Whi]^T + c.
// BM=128 BN=128 BK=64, 256 threads, 3-stage cp.async, SW128, ldsm.x4.
// grid (4, 64) = 256 CTAs. Sources selected per K-tile (no copies).
// ============================================================
#define BM 128
#define BN 128
#define BK 64
#define STAGE_A (BM * 128)
#define STAGE_B (BN * 128)
#define STAGE   (STAGE_A + STAGE_B)   // 32 KB
#define NSTAGE  3
#define GEMM_SMEM (NSTAGE * STAGE)    // 96 KB
#define NKT (KP / BK)                 // 24

__global__ __launch_bounds__(256, 2) void k_gemm_q2_mma() {
    extern __shared__ char smem[];
    const uint32_t sbase = smem_to_u32(smem);

    const int t    = threadIdx.x;
    const int lane = t & 31;
    const int wid  = t >> 5;
    const int wm   = wid & 1;
    const int wn   = wid >> 1;
    const int gid  = lane >> 2;
    const int qid  = lane & 3;

    const int n0 = blockIdx.x * BN;
    const int m0 = blockIdx.y * BM;

    const int row_ld = t >> 1;
    const int u0     = (t & 1) * 4;

    const size_t aoff = (size_t)(m0 + row_ld) * D + u0 * 8;
    const size_t boff = (size_t)(n0 + row_ld) * D + u0 * 8;

    uint32_t adst[4], bdst[4];
#pragma unroll
    for (int i = 0; i < 4; i++) {
        const int u = u0 + i;
        const uint32_t sw = ((uint32_t)(u ^ (row_ld & 7))) << 4;
        adst[i] = sbase + row_ld * 128 + sw;
        bdst[i] = sbase + STAGE_A + row_ld * 128 + sw;
    }

    const int lr   = lane & 7;
    const int half = (lane >> 3) & 1;
    const int kh   = (lane >> 4) & 1;
    int arow_f[4];
#pragma unroll
    for (int mt = 0; mt < 4; mt++) arow_f[mt] = wm * 64 + mt * 16 + half * 8 + lr;
    const int bmtx   = lane >> 3;
    const int bntoff = bmtx >> 1;
    const int bkh    = bmtx & 1;
    int brow_f[2];
#pragma unroll
    for (int p = 0; p < 2; p++) brow_f[p] = wn * 32 + (p * 2 + bntoff) * 8 + lr;

    float acc[4][4][4];
#pragma unroll
    for (int i = 0; i < 4; i++)
#pragma unroll
        for (int j = 0; j < 4; j++)
#pragma unroll
            for (int r = 0; r < 4; r++) acc[i][j][r] = 0.f;

#pragma unroll
    for (int s = 0; s < 2; s++) {
        const uint32_t soff = (uint32_t)(s * STAGE);
        const int ko = s * BK;
        const __nv_bfloat16* Ab = a_src(ko) + aoff;
        const __nv_bfloat16* Bb = b_src(ko) + boff;
#pragma unroll
        for (int i = 0; i < 4; i++) CP_ASYNC_16(adst[i] + soff, Ab + i * 8);
#pragma unroll
        for (int i = 0; i < 4; i++) CP_ASYNC_16(bdst[i] + soff, Bb + i * 8);
        CP_COMMIT();
    }

    for (int kt = 0; kt < NKT; kt++) {
        CP_WAIT1();
        __syncthreads();

        const int s = kt % NSTAGE;
        const uint32_t Asm = sbase + (uint32_t)(s * STAGE);
        const uint32_t Bsm = Asm + STAGE_A;
#pragma unroll
        for (int ks = 0; ks < 4; ks++) {
            uint32_t af[4][4];
#pragma unroll
            for (int mt = 0; mt < 4; mt++) {
                const int row = arow_f[mt];
                const int u = ks * 2 + kh;
                ldsm_x4(af[mt][0], af[mt][1], af[mt][2], af[mt][3],
                        Asm + row * 128 + (((uint32_t)(u ^ (row & 7))) << 4));
            }
            uint32_t bf[4][2];
#pragma unroll
            for (int p = 0; p < 2; p++) {
                const int row = brow_f[p];
                const int u = ks * 2 + bkh;
                ldsm_x4(bf[p * 2][0], bf[p * 2][1], bf[p * 2 + 1][0], bf[p * 2 + 1][1],
                        Bsm + row * 128 + (((uint32_t)(u ^ (row & 7))) << 4));
            }
#pragma unroll
            for (int mt = 0; mt < 4; mt++)
#pragma unroll
                for (int nt = 0; nt < 4; nt++)
                    mma_bf16_16816(acc[mt][nt], af[mt], bf[nt]);
        }

        if (kt + 2 < NKT) {
            const uint32_t soff = (uint32_t)(((kt + 2) % NSTAGE) * STAGE);
            const int ko = (kt + 2) * BK;
            const __nv_bfloat16* Ab = a_src(ko) + aoff;
            const __nv_bfloat16* Bb = b_src(ko) + boff;
#pragma unroll
            for (int i = 0; i < 4; i++) CP_ASYNC_16(adst[i] + soff, Ab + i * 8);
#pragma unroll
            for (int i = 0; i < 4; i++) CP_ASYNC_16(bdst[i] + soff, Bb + i * 8);
        }
        CP_COMMIT();
    }

#pragma unroll
    for (int mt = 0; mt < 4; mt++) {
        const int row0 = m0 + wm * 64 + mt * 16 + gid;
#pragma unroll
        for (int nt = 0; nt < 4; nt++) {
            const int col0 = n0 + wn * 32 + nt * 8 + qid * 2;
            const float c0 = g_c[col0], c1 = g_c[col0 + 1];
            float2 v0 = make_float2(acc[mt][nt][0] + c0, acc[mt][nt][1] + c1);
            float2 v1 = make_float2(acc[mt][nt][2] + c0, acc[mt][nt][3] + c1);
            *(float2*)(g_q2 + (size_t)row0 * D + col0)       = v0;
            *(float2*)(g_q2 + (size_t)(row0 + 8) * D + col0) = v1;
        }
    }
}

// ============================================================
// Kernel 4 (R11 + __stcs out): per-row attention + blend.
// keys/values via __ldcs (use-once), out via __stcs (write-once).
// ============================================================
__global__ __launch_bounds__(256) void k_attention(const float* __restrict__ x,
                                                   const float* __restrict__ keys,
                                                   const float* __restrict__ values,
                                                   float* __restrict__ out) {
    __shared__ __align__(16) float xs[D];
    __shared__ __align__(16) float q2s[D];
    __shared__ float att_s[KNN];
    __shared__ float warp_red[8];
    __shared__ float qb2_sh;

    const int b    = blockIdx.x;
    const int t    = threadIdx.x;
    const int lane = t & 31;
    const int w    = t >> 5;

    if (t < 128) {
        ((float4*)xs)[t] = ((const float4*)(x + (size_t)b * D))[t];
    } else {
        ((float4*)q2s)[t - 128] = ((const float4*)(g_q2 + (size_t)b * D))[t - 128];
    }
    __syncthreads();

    {
        float p = xs[t] * g_u[t] + xs[t + 256] * g_u[t + 256];
#pragma unroll
        for (int o = 16; o; o >>= 1) p += __shfl_xor_sync(0xffffffffu, p, o);
        if (lane == 0) warp_red[w] = p;
        __syncthreads();
        if (t == 0) {
            float s = 0.f;
#pragma unroll
            for (int i = 0; i < 8; i++) s += warp_red[i];
            qb2_sh = s + g_s0;
        }
        __syncthreads();
    }

    const float4* q2s4 = (const float4*)q2s;
    const float* kbase = keys + (size_t)b * KNN * D;
#pragma unroll
    for (int kk = 0; kk < 4; kk++) {
        const int k = w * 4 + kk;
        const float4* kr = (const float4*)(kbase + (size_t)k * D);
        float p = 0.f;
#pragma unroll
        for (int i = 0; i < 4; i++) {
            float4 kv = __ldcs(kr + lane + 32 * i);
            float4 qv = q2s4[lane + 32 * i];
            p += kv.x * qv.x + kv.y * qv.y + kv.z * qv.z + kv.w * qv.w;
        }
#pragma unroll
        for (int o = 16; o; o >>= 1) p += __shfl_xor_sync(0xffffffffu, p, o);
        if (lane == 0) att_s[k] = (p + qb2_sh) * SCORE_SCALE;
    }
    __syncthreads();

    if (t < 32) {
        float s = att_s[t];
        float m = s;
#pragma unroll
        for (int o = 16; o; o >>= 1) m = fmaxf(m, __shfl_xor_sync(0xffffffffu, m, o));
        float e = expf(s - m);
        float sum = e;
#pragma unroll
        for (int o = 16; o; o >>= 1) sum += __shfl_xor_sync(0xffffffffu, sum, o);
        att_s[t] = e / sum;
    }
    __syncthreads();

    const float* vbase = values + (size_t)b * KNN * D + 2 * t;
    float ax = 0.f, ay = 0.f;
#pragma unroll
    for (int k = 0; k < KNN; k++) {
        float a = att_s[k];
        float2 v = __ldcs((const float2*)(vbase + (size_t)k * D));
        ax += a * v.x;
        ay += a * v.y;
    }
    float2 xv = *(const float2*)&xs[2 * t];
    float2 o;
    o.x = 0.5f * xv.x + 0.5f * ax;
    o.y = 0.5f * xv.y + 0.5f * ay;
    __stcs((float2*)(out + (size_t)b * D + 2 * t), o);
}

// ============================================================
extern "C" void kernel_launch(void* const* d_in, const int* in_sizes, int n_in,
                              void* d_out, int out_size) {
    const float* x      = (const float*)d_in[0];
    const float* keys   = (const float*)d_in[1];
    const float* values = (const float*)d_in[2];
    const float* w1     = (const float*)d_in[3];
    const float* b1     = (const float*)d_in[4];
    const float* w2     = (const float*)d_in[5];
    const float* b2     = (const float*)d_in[6];
    float* out          = (float*)d_out;

    (void)in_sizes; (void)n_in; (void)out_size;

    cudaFuncSetAttribute(k_gemm_q2_mma, cudaFuncAttributeMaxDynamicSharedMemorySize,
                         GEMM_SMEM);

    k_split_x<<<(B_ROWS * D) / (256 * 8), 256>>>(x);
    k_prep_W<<<PREP_GRID, 256>>>(w1, w2, b1, b2);
    k_gemm_q2_mma<<<dim3(4, 64), 256, GEMM_SMEM>>>();
    k_attention<<<B_ROWS, 256>>>(x, keys, values, out);
}

// round 14
// speedup vs baseline: 1.1868x; 1.1868x over previous
#include <cuda_runtime.h>
#include <cuda_bf16.h>
#include <cstdint>
#include <math.h>

#define B_ROWS 8192
#define KNN    32
#define D      512
#define KP     1536   // logical concatenated K (3*D)

// 1/sqrt(512)
#define SCORE_SCALE 0.044194173824159220f

// -------- device scratch (allocation-free) --------
__device__ __align__(16) __nv_bfloat16 g_W_hi[(size_t)D * D];     // [n][d]
__device__ __align__(16) __nv_bfloat16 g_W_lo[(size_t)D * D];     // [n][d]
__device__ __align__(16) __nv_bfloat16 g_x_hi[(size_t)B_ROWS * D];
__device__ __align__(16) __nv_bfloat16 g_x_lo[(size_t)B_ROWS * D];
__device__ float g_c[D];
__device__ float g_u[D];
__device__ float g_s0;
__device__ __align__(16) float g_q2[(size_t)B_ROWS * D];

// ---- PTX helpers ----
__device__ __forceinline__ uint32_t smem_to_u32(const void* p) {
    uint32_t a;
    asm("{ .reg .u64 tmp; cvta.to.shared.u64 tmp, %1; cvt.u32.u64 %0, tmp; }"
        : "=r"(a) : "l"(p));
    return a;
}
__device__ __forceinline__ void mma_bf16_16816(float* d, const uint32_t* a, const uint32_t* b) {
    asm volatile(
        "mma.sync.aligned.m16n8k16.row.col.f32.bf16.bf16.f32 "
        "{%0,%1,%2,%3}, {%4,%5,%6,%7}, {%8,%9}, {%0,%1,%2,%3};"
        : "+f"(d[0]), "+f"(d[1]), "+f"(d[2]), "+f"(d[3])
        : "r"(a[0]), "r"(a[1]), "r"(a[2]), "r"(a[3]), "r"(b[0]), "r"(b[1]));
}
__device__ __forceinline__ void ldsm_x4(uint32_t& r0, uint32_t& r1, uint32_t& r2, uint32_t& r3,
                                        uint32_t addr) {
    asm volatile("ldmatrix.sync.aligned.m8n8.x4.shared.b16 {%0,%1,%2,%3}, [%4];"
                 : "=r"(r0), "=r"(r1), "=r"(r2), "=r"(r3) : "r"(addr));
}
#define CP_ASYNC_16(dst, src) \
    asm volatile("cp.async.cg.shared.global [%0], [%1], 16;" :: "r"(dst), "l"(src))
#define CP_COMMIT() asm volatile("cp.async.commit_group;" ::: "memory")
#define CP_WAIT1()  asm volatile("cp.async.wait_group 1;" ::: "memory")

// per-K'-tile source selection (logical [x_hi | x_hi | x_lo], [W_hi | W_lo | W_hi])
__device__ __forceinline__ const __nv_bfloat16* a_src(int ko) {
    return (ko < 1024) ? (g_x_hi + (ko & 511)) : (g_x_lo + (ko - 1024));
}
__device__ __forceinline__ const __nv_bfloat16* b_src(int ko) {
    return (ko < 512) ? (g_W_hi + ko)
         : (ko < 1024) ? (g_W_lo + (ko - 512))
                       : (g_W_hi + (ko - 1024));
}

// ============================================================
// Kernel 1 (merged): blocks [0,256) = prep_W 32x32 tile
// (register double-buffered k-loop); blocks [256,288) = prep_aux.
// Both roles are compute/latency-type — no streaming role mixed in.
// ============================================================
#define PREP_W_BLOCKS   256
#define PREP_AUX_BLOCKS 32
#define PREP_GRID (PREP_W_BLOCKS + PREP_AUX_BLOCKS)

__global__ __launch_bounds__(256) void k_prep_W(const float* __restrict__ w1,
                                                const float* __restrict__ w2,
                                                const float* __restrict__ b1,
                                                const float* __restrict__ b2) {
    const int bid = blockIdx.x;
    const int t   = threadIdx.x;

    if (bid < PREP_W_BLOCKS) {
        // ---- role: prep_W (double-buffered loads) ----
        __shared__ __align__(16) float As[32][36];
        __shared__ __align__(16) float Bs[32][36];
        const int tx = t & 31;
        const int ty = t >> 5;
        const int m0 = (bid >> 4) * 32;
        const int n0 = (bid & 15) * 32;
        const int lrow = t >> 3;
        const int lcol = (t & 7) * 4;

        float acc[4] = {0.f, 0.f, 0.f, 0.f};

        const float* w1p = w1 + (size_t)lrow * D + m0 + lcol;
        const float* w2p = w2 + (size_t)lrow * D + n0 + lcol;

        float4 a = *(const float4*)(w1p);
        float4 b = *(const float4*)(w2p);

        for (int k0 = 0; k0 < D; k0 += 32) {
            *(float4*)&As[lrow][lcol] = a;
            *(float4*)&Bs[lrow][lcol] = b;
            __syncthreads();
            if (k0 + 32 < D) {
                a = *(const float4*)(w1p + (size_t)(k0 + 32) * D);
                b = *(const float4*)(w2p + (size_t)(k0 + 32) * D);
            }
#pragma unroll
            for (int k = 0; k < 32; k++) {
                const float bv = Bs[k][tx];
#pragma unroll
                for (int i = 0; i < 4; i++) acc[i] += As[k][ty * 4 + i] * bv;
            }
            __syncthreads();
        }
        const int mbase = m0 + ty * 4;
        const int n = n0 + tx;
        __nv_bfloat16 h4[4], l4[4];
#pragma unroll
        for (int i = 0; i < 4; i++) {
            h4[i] = __float2bfloat16_rn(acc[i]);
            l4[i] = __float2bfloat16_rn(acc[i] - __bfloat162float(h4[i]));
        }
        *(uint2*)(g_W_hi + (size_t)n * D + mbase) = *(const uint2*)h4;
        *(uint2*)(g_W_lo + (size_t)n * D + mbase) = *(const uint2*)l4;

    } else {
        // ---- role: prep_aux ----
        const int ab = bid - PREP_W_BLOCKS;
        const int dl = t >> 4;
        const int el = t & 15;
        const int d = ab * 16 + dl;
        float cacc = 0.f, uacc = 0.f;
#pragma unroll 4
        for (int e = el; e < D; e += 16) {
            cacc += b1[e] * w2[(size_t)e * D + d];
            uacc += b2[e] * w1[(size_t)e * D + d];
        }
#pragma unroll
        for (int o = 8; o; o >>= 1) {
            cacc += __shfl_down_sync(0xffffffffu, cacc, o, 16);
            uacc += __shfl_down_sync(0xffffffffu, uacc, o, 16);
        }
        if (el == 0) { g_c[d] = cacc; g_u[d] = uacc; }
        if (ab == 0 && t < 32) {
            float s = 0.f;
            for (int e = t; e < D; e += 32) s += b1[e] * b2[e];
#pragma unroll
            for (int o = 16; o; o >>= 1) s += __shfl_xor_sync(0xffffffffu, s, o);
            if (t == 0) g_s0 = s;
        }
    }
}

// ============================================================
// Kernel 2b: split x -> g_x_hi / g_x_lo.
// ============================================================
__global__ __launch_bounds__(256) void k_split_x(const float* __restrict__ x) {
    const size_t base = ((size_t)blockIdx.x * 256 + threadIdx.x) * 8;
    float4 v0 = *(const float4*)(x + base);
    float4 v1 = *(const float4*)(x + base + 4);
    float f[8] = {v0.x, v0.y, v0.z, v0.w, v1.x, v1.y, v1.z, v1.w};
    __nv_bfloat16 hi[8], lo[8];
#pragma unroll
    for (int i = 0; i < 8; i++) {
        hi[i] = __float2bfloat16_rn(f[i]);
        lo[i] = __float2bfloat16_rn(f[i] - __bfloat162float(hi[i]));
    }
    *(uint4*)(g_x_hi + base) = *(const uint4*)hi;
    *(uint4*)(g_x_lo + base) = *(const uint4*)lo;
}

// ============================================================
// Kernel 3 (R9/R11 exact): q2 = [xhi|xhi|xlo] @ [Whi|Wlo|Whi]^T + c.
// BM=128 BN=128 BK=64, 256 threads, 3-stage cp.async, SW128, ldsm.x4.
// grid (4, 64) = 256 CTAs. Sources selected per K-tile (no copies).
// ============================================================
#define BM 128
#define BN 128
#define BK 64
#define STAGE_A (BM * 128)
#define STAGE_B (BN * 128)
#define STAGE   (STAGE_A + STAGE_B)   // 32 KB
#define NSTAGE  3
#define GEMM_SMEM (NSTAGE * STAGE)    // 96 KB
#define NKT (KP / BK)                 // 24

__global__ __launch_bounds__(256, 2) void k_gemm_q2_mma() {
    extern __shared__ char smem[];
    const uint32_t sbase = smem_to_u32(smem);

    const int t    = threadIdx.x;
    const int lane = t & 31;
    const int wid  = t >> 5;
    const int wm   = wid & 1;
    const int wn   = wid >> 1;
    const int gid  = lane >> 2;
    const int qid  = lane & 3;

    const int n0 = blockIdx.x * BN;
    const int m0 = blockIdx.y * BM;

    const int row_ld = t >> 1;
    const int u0     = (t & 1) * 4;

    const size_t aoff = (size_t)(m0 + row_ld) * D + u0 * 8;
    const size_t boff = (size_t)(n0 + row_ld) * D + u0 * 8;

    uint32_t adst[4], bdst[4];
#pragma unroll
    for (int i = 0; i < 4; i++) {
        const int u = u0 + i;
        const uint32_t sw = ((uint32_t)(u ^ (row_ld & 7))) << 4;
        adst[i] = sbase + row_ld * 128 + sw;
        bdst[i] = sbase + STAGE_A + row_ld * 128 + sw;
    }

    const int lr   = lane & 7;
    const int half = (lane >> 3) & 1;
    const int kh   = (lane >> 4) & 1;
    int arow_f[4];
#pragma unroll
    for (int mt = 0; mt < 4; mt++) arow_f[mt] = wm * 64 + mt * 16 + half * 8 + lr;
    const int bmtx   = lane >> 3;
    const int bntoff = bmtx >> 1;
    const int bkh    = bmtx & 1;
    int brow_f[2];
#pragma unroll
    for (int p = 0; p < 2; p++) brow_f[p] = wn * 32 + (p * 2 + bntoff) * 8 + lr;

    float acc[4][4][4];
#pragma unroll
    for (int i = 0; i < 4; i++)
#pragma unroll
        for (int j = 0; j < 4; j++)
#pragma unroll
            for (int r = 0; r < 4; r++) acc[i][j][r] = 0.f;

#pragma unroll
    for (int s = 0; s < 2; s++) {
        const uint32_t soff = (uint32_t)(s * STAGE);
        const int ko = s * BK;
        const __nv_bfloat16* Ab = a_src(ko) + aoff;
        const __nv_bfloat16* Bb = b_src(ko) + boff;
#pragma unroll
        for (int i = 0; i < 4; i++) CP_ASYNC_16(adst[i] + soff, Ab + i * 8);
#pragma unroll
        for (int i = 0; i < 4; i++) CP_ASYNC_16(bdst[i] + soff, Bb + i * 8);
        CP_COMMIT();
    }

    for (int kt = 0; kt < NKT; kt++) {
        CP_WAIT1();
        __syncthreads();

        const int s = kt % NSTAGE;
        const uint32_t Asm = sbase + (uint32_t)(s * STAGE);
        const uint32_t Bsm = Asm + STAGE_A;
#pragma unroll
        for (int ks = 0; ks < 4; ks++) {
            uint32_t af[4][4];
#pragma unroll
            for (int mt = 0; mt < 4; mt++) {
                const int row = arow_f[mt];
                const int u = ks * 2 + kh;
                ldsm_x4(af[mt][0], af[mt][1], af[mt][2], af[mt][3],
                        Asm + row * 128 + (((uint32_t)(u ^ (row & 7))) << 4));
            }
            uint32_t bf[4][2];
#pragma unroll
            for (int p = 0; p < 2; p++) {
                const int row = brow_f[p];
                const int u = ks * 2 + bkh;
                ldsm_x4(bf[p * 2][0], bf[p * 2][1], bf[p * 2 + 1][0], bf[p * 2 + 1][1],
                        Bsm + row * 128 + (((uint32_t)(u ^ (row & 7))) << 4));
            }
#pragma unroll
            for (int mt = 0; mt < 4; mt++)
#pragma unroll
                for (int nt = 0; nt < 4; nt++)
                    mma_bf16_16816(acc[mt][nt], af[mt], bf[nt]);
        }

        if (kt + 2 < NKT) {
            const uint32_t soff = (uint32_t)(((kt + 2) % NSTAGE) * STAGE);
            const int ko = (kt + 2) * BK;
            const __nv_bfloat16* Ab = a_src(ko) + aoff;
            const __nv_bfloat16* Bb = b_src(ko) + boff;
#pragma unroll
            for (int i = 0; i < 4; i++) CP_ASYNC_16(adst[i] + soff, Ab + i * 8);
#pragma unroll
            for (int i = 0; i < 4; i++) CP_ASYNC_16(bdst[i] + soff, Bb + i * 8);
        }
        CP_COMMIT();
    }

#pragma unroll
    for (int mt = 0; mt < 4; mt++) {
        const int row0 = m0 + wm * 64 + mt * 16 + gid;
#pragma unroll
        for (int nt = 0; nt < 4; nt++) {
            const int col0 = n0 + wn * 32 + nt * 8 + qid * 2;
            const float c0 = g_c[col0], c1 = g_c[col0 + 1];
            float2 v0 = make_float2(acc[mt][nt][0] + c0, acc[mt][nt][1] + c1);
            float2 v1 = make_float2(acc[mt][nt][2] + c0, acc[mt][nt][3] + c1);
            *(float2*)(g_q2 + (size_t)row0 * D + col0)       = v0;
            *(float2*)(g_q2 + (size_t)(row0 + 8) * D + col0) = v1;
        }
    }
}

// ============================================================
// Kernel 4 (R11 exact): per-row attention + blend, __ldcs streaming
// on keys/values, normal cached stores for out.
// ============================================================
__global__ __launch_bounds__(256) void k_attention(const float* __restrict__ x,
                                                   const float* __restrict__ keys,
                                                   const float* __restrict__ values,
                                                   float* __restrict__ out) {
    __shared__ __align__(16) float xs[D];
    __shared__ __align__(16) float q2s[D];
    __shared__ float att_s[KNN];
    __shared__ float warp_red[8];
    __shared__ float qb2_sh;

    const int b    = blockIdx.x;
    const int t    = threadIdx.x;
    const int lane = t & 31;
    const int w    = t >> 5;

    if (t < 128) {
        ((float4*)xs)[t] = ((const float4*)(x + (size_t)b * D))[t];
    } else {
        ((float4*)q2s)[t - 128] = ((const float4*)(g_q2 + (size_t)b * D))[t - 128];
    }
    __syncthreads();

    {
        float p = xs[t] * g_u[t] + xs[t + 256] * g_u[t + 256];
#pragma unroll
        for (int o = 16; o; o >>= 1) p += __shfl_xor_sync(0xffffffffu, p, o);
        if (lane == 0) warp_red[w] = p;
        __syncthreads();
        if (t == 0) {
            float s = 0.f;
#pragma unroll
            for (int i = 0; i < 8; i++) s += warp_red[i];
            qb2_sh = s + g_s0;
        }
        __syncthreads();
    }

    const float4* q2s4 = (const float4*)q2s;
    const float* kbase = keys + (size_t)b * KNN * D;
#pragma unroll
    for (int kk = 0; kk < 4; kk++) {
        const int k = w * 4 + kk;
        const float4* kr = (const float4*)(kbase + (size_t)k * D);
        float p = 0.f;
#pragma unroll
        for (int i = 0; i < 4; i++) {
            float4 kv = __ldcs(kr + lane + 32 * i);
            float4 qv = q2s4[lane + 32 * i];
            p += kv.x * qv.x + kv.y * qv.y + kv.z * qv.z + kv.w * qv.w;
        }
#pragma unroll
        for (int o = 16; o; o >>= 1) p += __shfl_xor_sync(0xffffffffu, p, o);
        if (lane == 0) att_s[k] = (p + qb2_sh) * SCORE_SCALE;
    }
    __syncthreads();

    if (t < 32) {
        float s = att_s[t];
        float m = s;
#pragma unroll
        for (int o = 16; o; o >>= 1) m = fmaxf(m, __shfl_xor_sync(0xffffffffu, m, o));
        float e = expf(s - m);
        float sum = e;
#pragma unroll
        for (int o = 16; o; o >>= 1) sum += __shfl_xor_sync(0xffffffffu, sum, o);
        att_s[t] = e / sum;
    }
    __syncthreads();

    const float* vbase = values + (size_t)b * KNN * D + 2 * t;
    float ax = 0.f, ay = 0.f;
#pragma unroll
    for (int k = 0; k < KNN; k++) {
        float a = att_s[k];
        float2 v = __ldcs((const float2*)(vbase + (size_t)k * D));
        ax += a * v.x;
        ay += a * v.y;
    }
    float2 xv = *(const float2*)&xs[2 * t];
    float2 o;
    o.x = 0.5f * xv.x + 0.5f * ax;
    o.y = 0.5f * xv.y + 0.5f * ay;
    *(float2*)(out + (size_t)b * D + 2 * t) = o;
}

// ============================================================
extern "C" void kernel_launch(void* const* d_in, const int* in_sizes, int n_in,
                              void* d_out, int out_size) {
    const float* x      = (const float*)d_in[0];
    const float* keys   = (const float*)d_in[1];
    const float* values = (const float*)d_in[2];
    const float* w1     = (const float*)d_in[3];
    const float* b1     = (const float*)d_in[4];
    const float* w2     = (const float*)d_in[5];
    const float* b2     = (const float*)d_in[6];
    float* out          = (float*)d_out;

    (void)in_sizes; (void)n_in; (void)out_size;

    cudaFuncSetAttribute(k_gemm_q2_mma, cudaFuncAttributeMaxDynamicSharedMemorySize,
                         GEMM_SMEM);

    k_split_x<<<(B_ROWS * D) / (256 * 8), 256>>>(x);
    k_prep_W<<<PREP_GRID, 256>>>(w1, w2, b1, b2);
    k_gemm_q2_mma<<<dim3(4, 64), 256, GEMM_SMEM>>>();
    k_attention<<<B_ROWS, 256>>>(x, keys, values, out);
}